// round 11
// baseline (speedup 1.0000x reference)
#include <cuda_runtime.h>
#include <math.h>

// ---- problem config ----
#define BB 4
#define NN 16384
#define REG_CH 76
#define POST 128
#define PSEL 256               // candidate budget (128th kept ~rank 130; 2x margin)
#define MWS (PSEL / 32)        // sup words per row = 8
#define CANDP 512              // primary sort size
#define CANDM 1024             // mid fallback
#define CANDF 4096             // max fallback
#define NMS_THRESH 0.8f
#define TWO_PI_F 6.2831853071795864769f
#define PI_F 3.14159265358979323846f
#define APC_F 0.52359877559829887308f       // 2pi/12
#define APC_HALF_F 0.26179938779914943654f  // pi/12

#define RSTRIDE 79             // 76 reg + 3 xyz; odd -> conflict-free LDS

// ---- dynamic smem layout (bytes); regions time-multiplexed ----
// phase 1 (select/sort): cand [81920,114688)
// phase 2 (copy/decode): rowsbuf [0,80896) | cand | score/bev/sar/box high
// phase 3 (mask/greedy): sup [0,8192) | bev/sar/box/score high
#define OFF_ROWS   0                        // 256*79*4 = 80896
#define OFF_SUP    0                        // 256*8*4 = 8192 (phase 3)
#define OFF_CAND   81920                    // 4096 u64 = 32768 -> 114688
#define OFF_SCORE  114688                   // 256 f32 = 1024
#define OFF_BEV4   115712                   // 256 float4 = 4096
#define OFF_SAR    119808                   // 256 f32 = 1024
#define OFF_BOX    120832                   // 256*7 f32 = 7168 -> 128000
#define SMEM_BYTES 128000

__device__ __forceinline__ unsigned desc_key(float f) {
    unsigned u = __float_as_uint(f);
    unsigned asc = (u & 0x80000000u) ? ~u : (u | 0x80000000u);
    return ~asc;   // ascending key order == descending score order
}
__device__ __forceinline__ float key_to_score(unsigned desc) {
    unsigned asc = ~desc;
    unsigned u = (asc & 0x80000000u) ? (asc ^ 0x80000000u) : ~asc;
    return __uint_as_float(u);
}

// hybrid bitonic sort, n power of 2 (512..4096), 1024 threads.
__device__ __forceinline__ void bitonic_hybrid(unsigned long long* a, int n, int tid) {
    const int lane = tid & 31;
    const int wid = tid >> 5;
    for (int k = 2; k <= n; k <<= 1) {
        for (int j = k >> 1; j >= 32; j >>= 1) {
            for (int i = tid; i < n; i += 1024) {
                int ixj = i ^ j;
                if (ixj > i) {
                    unsigned long long x = a[i], y = a[ixj];
                    bool asc = ((i & k) == 0);
                    if ((x > y) == asc) { a[i] = y; a[ixj] = x; }
                }
            }
            __syncthreads();
        }
        int jtop = (k >> 1) < 16 ? (k >> 1) : 16;
        for (int g = wid; g < (n >> 5); g += 32) {
            int i = (g << 5) + lane;
            unsigned long long v = a[i];
            bool asc = ((i & k) == 0);
            for (int j = jtop; j >= 1; j >>= 1) {
                unsigned long long p = __shfl_xor_sync(0xffffffffu, v, j);
                bool takemin = (((lane & j) == 0) == asc);
                v = takemin ? (v < p ? v : p) : (v > p ? v : p);
            }
            a[i] = v;
        }
        __syncthreads();
    }
}

// ============================================================
// One block per image.
// ============================================================
__global__ void __launch_bounds__(1024, 1)
fused_kernel(const float* __restrict__ scores,
             const float* __restrict__ reg,
             const float* __restrict__ xyz,
             const float* __restrict__ anchor,
             float* __restrict__ out) {
    extern __shared__ char sm[];
    unsigned long long* cand = (unsigned long long*)(sm + OFF_CAND);
    float* rowsbuf = (float*)(sm + OFF_ROWS);
    unsigned* sup = (unsigned*)(sm + OFF_SUP);
    float4* sbev = (float4*)(sm + OFF_BEV4);     // (x1,z1,x2,z2)
    float* sar = (float*)(sm + OFF_SAR);
    float* boxS = (float*)(sm + OFF_BOX);
    float* scoreS = (float*)(sm + OFF_SCORE);

    __shared__ unsigned wsum[32];
    __shared__ unsigned bcast;
    __shared__ unsigned zrow[MWS];    // per-box "suppresses anything" bitmap
    __shared__ int sCnt, sKeepCnt;
    __shared__ int keep[POST];

    const int img = blockIdx.x;
    const int tid = threadIdx.x;
    const int lane = tid & 31;
    const int wid = tid >> 5;
    const float4* sc4 = (const float4*)(scores + (size_t)img * NN);

    // ========== Stage A: register keys + bisection threshold ==========
    unsigned uk[16];
    {
        #pragma unroll
        for (int c = 0; c < 4; c++) {
            float4 v = sc4[c * 1024 + tid];
            uk[c * 4 + 0] = desc_key(v.x);
            uk[c * 4 + 1] = desc_key(v.y);
            uk[c * 4 + 2] = desc_key(v.z);
            uk[c * 4 + 3] = desc_key(v.w);
        }
    }
    if (tid == 0) sCnt = 0;
    if (tid < MWS) zrow[tid] = 0;

    unsigned lo = 0u, hi = 0xffffffffu;
    unsigned chi = NN;   // count at hi
    for (int it = 0; it < 32; it++) {
        unsigned mid = lo + ((hi - lo) >> 1);
        // block-wide count of keys <= mid
        unsigned c16 = 0;
        #pragma unroll
        for (int e = 0; e < 16; e++) c16 += (uk[e] <= mid);
        unsigned wc = __reduce_add_sync(0xffffffffu, c16);
        if (lane == 0) wsum[wid] = wc;
        __syncthreads();
        if (wid == 0) {
            unsigned t = wsum[lane];
            t = __reduce_add_sync(0xffffffffu, t);
            if (lane == 0) bcast = t;
        }
        __syncthreads();
        unsigned cnt = bcast;
        if (cnt >= PSEL) {
            hi = mid; chi = cnt;
            if (cnt <= CANDP) break;
        } else {
            lo = mid;
        }
        if (hi - lo <= 1u) break;
        __syncthreads();   // protect bcast/wsum reuse
    }
    const unsigned T = hi;
    const int C = (int)chi;
    __syncthreads();

    // ========== warp-aggregated compaction into cand ==========
    const int NS = (C <= CANDP) ? CANDP : ((C <= CANDM) ? CANDM : CANDF);
    {
        unsigned s = 0;
        #pragma unroll
        for (int e = 0; e < 16; e++) s += (uk[e] <= T);
        // warp exclusive prefix of s
        unsigned pfx = s;
        #pragma unroll
        for (int d = 1; d < 32; d <<= 1) {
            unsigned y = __shfl_up_sync(0xffffffffu, pfx, d);
            if (lane >= d) pfx += y;
        }
        unsigned wtot = __shfl_sync(0xffffffffu, pfx, 31);
        unsigned excl = pfx - s;
        unsigned base = 0;
        if (lane == 0 && wtot > 0) base = atomicAdd(&sCnt, (int)wtot);
        base = __shfl_sync(0xffffffffu, base, 0);
        int pos = (int)(base + excl);
        #pragma unroll
        for (int e = 0; e < 16; e++) {
            if (uk[e] <= T) {
                int idx = (((e >> 2) * 1024 + tid) << 2) + (e & 3);
                if (pos < CANDF)
                    cand[pos] = ((unsigned long long)uk[e] << 32) | (unsigned)idx;
                pos++;
            }
        }
    }
    __syncthreads();
    for (int p = C + tid; p < NS; p += 1024)
        cand[p] = 0xffffffffffffffffull;
    __syncthreads();

    bitonic_hybrid(cand, NS, tid);

    // ========== Stage B1: coalesced copy of top-256 rows to smem ==========
    for (int rr = wid; rr < PSEL; rr += 32) {
        unsigned long long key = cand[rr];          // uniform -> broadcast LDS
        int idx = (int)(key & 0xffffffffu);
        const float* r = reg + (size_t)(img * NN + idx) * REG_CH;
        float* dst = rowsbuf + rr * RSTRIDE;
        dst[lane]      = r[lane];
        dst[32 + lane] = r[32 + lane];
        if (lane < 12)       dst[64 + lane] = r[64 + lane];
        else if (lane < 15)  dst[64 + lane] = xyz[(size_t)(img * NN + idx) * 3 + (lane - 12)];
        if (lane == 15) scoreS[rr] = key_to_score((unsigned)(key >> 32));
    }
    __syncthreads();

    // ========== Stage B2: decode from smem (thread-per-row, conflict-free) ==========
    const float ah = anchor[0], aw = anchor[1], al = anchor[2];
    if (tid < PSEL) {
        const float* r = rowsbuf + tid * RSTRIDE;

        int xb = 0; float bv = r[0];
        #pragma unroll
        for (int t = 1; t < 12; t++) if (r[t] > bv) { bv = r[t]; xb = t; }
        int zb = 0; bv = r[12];
        #pragma unroll
        for (int t = 1; t < 12; t++) if (r[12 + t] > bv) { bv = r[12 + t]; zb = t; }

        float pos_x = __fadd_rn(__fsub_rn(__fadd_rn(__fmul_rn((float)xb, 0.5f), 0.25f), 3.0f),
                                __fmul_rn(r[24 + xb], 0.5f));
        float pos_z = __fadd_rn(__fsub_rn(__fadd_rn(__fmul_rn((float)zb, 0.5f), 0.25f), 3.0f),
                                __fmul_rn(r[36 + zb], 0.5f));
        float x = __fadd_rn(pos_x, r[76]);
        float z = __fadd_rn(pos_z, r[78]);
        float y = __fadd_rn(r[77], r[48]);

        int rb = 0; bv = r[49];
        #pragma unroll
        for (int t = 1; t < 12; t++) if (r[49 + t] > bv) { bv = r[49 + t]; rb = t; }
        float ry = __fadd_rn(__fmul_rn((float)rb, APC_F),
                             __fmul_rn(r[61 + rb], APC_HALF_F));
        float rem = fmodf(ry, TWO_PI_F);
        if (rem != 0.0f && rem < 0.0f) rem = __fadd_rn(rem, TWO_PI_F);
        ry = rem;
        if (ry > PI_F) ry = __fsub_rn(ry, TWO_PI_F);

        float h = __fadd_rn(__fmul_rn(r[73], ah), ah);
        float w = __fadd_rn(__fmul_rn(r[74], aw), aw);
        float l = __fadd_rn(__fmul_rn(r[75], al), al);
        y = __fadd_rn(y, __fmul_rn(h, 0.5f));

        float* bo = boxS + tid * 7;
        bo[0] = x; bo[1] = y; bo[2] = z; bo[3] = h; bo[4] = w; bo[5] = l; bo[6] = ry;

        float x1 = __fsub_rn(x, __fmul_rn(l, 0.5f));
        float x2 = __fadd_rn(x, __fmul_rn(l, 0.5f));
        float z1 = __fsub_rn(z, __fmul_rn(w, 0.5f));
        float z2 = __fadd_rn(z, __fmul_rn(w, 0.5f));
        sbev[tid] = make_float4(x1, z1, x2, z2);
        sar[tid] = __fmul_rn(__fsub_rn(x2, x1), __fsub_rn(z2, z1));
    }
    __syncthreads();   // rowsbuf dead; sup may now overwrite [0,8192)

    // ========== Stage C: balanced pairwise suppression bitmask + zrow ==========
    // 128 row-pairs x 8 words = 1024 units; thread does (p, w) and (255-p, w)
    {
        const int pr = tid & 127;                // pair id
        const int w = tid >> 7;                  // word 0..7
        #pragma unroll
        for (int half = 0; half < 2; half++) {
            const int i = half ? (PSEL - 1 - pr) : pr;
            float4 bi = sbev[i];
            float ai = sar[i];
            unsigned bits = 0;
            int jbase = w << 5;
            if (jbase + 31 > i) {
                #pragma unroll 4
                for (int b = 0; b < 32; b++) {
                    int j = jbase + b;
                    if (j <= i) continue;
                    float4 bj = sbev[j];
                    float iw = fmaxf(__fsub_rn(fminf(bi.z, bj.z), fmaxf(bi.x, bj.x)), 0.0f);
                    float ih = fmaxf(__fsub_rn(fminf(bi.w, bj.w), fmaxf(bi.y, bj.y)), 0.0f);
                    float inter = __fmul_rn(iw, ih);
                    if (inter > 0.0f) {
                        float denom = __fsub_rn(__fadd_rn(ai, sar[j]), inter);
                        float iou = __fdiv_rn(inter, denom);
                        if (iou > NMS_THRESH) bits |= (1u << b);
                    }
                }
            }
            sup[i * MWS + w] = bits;
            if (bits) atomicOr(&zrow[i >> 5], 1u << (i & 31));
        }
    }
    __syncthreads();

    // ========== Stage D: bulk-skip greedy (warp 0) ==========
    if (wid == 0) {
        unsigned A = (lane < MWS) ? 0xffffffffu : 0u;   // alive bitmap
        unsigned Z = (lane < MWS) ? zrow[lane] : 0u;    // suppressor flags
        int cnt = 0;
        int w = 0;
        while (cnt < POST && w < MWS) {
            unsigned word = __shfl_sync(0xffffffffu, A, w);
            unsigned zw   = __shfl_sync(0xffffffffu, Z, w);
            unsigned danger = word & zw;
            if (danger == 0) {
                int nb = __popc(word);
                int take = min(nb, POST - cnt);
                if (lane < take) {
                    int bit = __fns(word, 0, lane + 1);
                    keep[cnt + lane] = (w << 5) + bit;
                }
                cnt += take;
                w++;
            } else {
                int bs = __ffs(danger) - 1;            // first alive suppressor
                unsigned prefix = word & ((1u << bs) - 1u);
                int nb = __popc(prefix);
                int take = min(nb, POST - cnt);
                if (lane < take) {
                    int bit = __fns(prefix, 0, lane + 1);
                    keep[cnt + lane] = (w << 5) + bit;
                }
                cnt += take;
                if (cnt >= POST) break;
                int bi = (w << 5) + bs;
                if (lane == 0) keep[cnt] = bi;
                cnt++;
                unsigned srow = (lane < MWS) ? sup[bi * MWS + lane] : 0u;
                A &= ~srow;
                if (lane == w) {
                    unsigned clr = (bs == 31) ? 0xffffffffu : ((1u << (bs + 1)) - 1u);
                    A &= ~clr;   // bits <= bs consumed
                }
            }
        }
        if (lane == 0) sKeepCnt = cnt;
    }
    __syncthreads();

    // ========== Stage E: gather output ==========
    const int cnt = sKeepCnt;
    float* ob = out + (size_t)img * POST * 7;
    float* os = out + (size_t)BB * POST * 7 + (size_t)img * POST;
    if (tid < POST) {
        int p = tid;
        if (p < cnt) {
            int ki = keep[p];
            const float* bo = boxS + ki * 7;
            #pragma unroll
            for (int c = 0; c < 7; c++) ob[p * 7 + c] = bo[c];
            os[p] = scoreS[ki];
        } else {
            #pragma unroll
            for (int c = 0; c < 7; c++) ob[p * 7 + c] = 0.0f;
            os[p] = 0.0f;
        }
    }
}

// ============================================================
extern "C" void kernel_launch(void* const* d_in, const int* in_sizes, int n_in,
                              void* d_out, int out_size) {
    const float* scores = (const float*)d_in[0];   // (B,N)
    const float* reg    = (const float*)d_in[1];   // (B,N,76)
    const float* xyz    = (const float*)d_in[2];   // (B,N,3)
    const float* anchor = (const float*)d_in[3];   // (3,)
    float* out = (float*)d_out;

    static bool attr_set = false;
    if (!attr_set) {
        cudaFuncSetAttribute(fused_kernel,
                             cudaFuncAttributeMaxDynamicSharedMemorySize,
                             SMEM_BYTES);
        attr_set = true;
    }

    fused_kernel<<<BB, 1024, SMEM_BYTES>>>(scores, reg, xyz, anchor, out);
}